// round 6
// baseline (speedup 1.0000x reference)
#include <cuda_runtime.h>
#include <cstdint>

// CausalRevIN, B=16, T=8192, C=128, f32, C innermost.
// out = clip((x-mean)/std, -100, 100); mean = cumsum(x)/n, n = max(cumsum(1-mask),1);
// std = sqrt(cumsum(((x-mean)*(1-mask))^2)/n); std<=1e-5 -> 1.
//
// v5: float2 channel-pair vectorization. Lane owns 2 adjacent channels ->
// LDG.64/STG.64 256B per warp, ~half the instructions per element of v4,
// and 1024 fat blocks (64ch x 256t) amortize the per-block sync overhead.

namespace {
constexpr int Bn = 16;
constexpr int Tn = 8192;
constexpr int Cn = 128;

constexpr int LANES   = 32;            // lanes; lane owns channels (2c, 2c+1)
constexpr int CPB     = 64;            // channels per block
constexpr int LINKS   = 32;            // T segments per chain
constexpr int TSEG    = Tn / LINKS;    // 256
constexpr int THREADS = 512;
constexpr int TPC     = THREADS / 32;  // 16 warps = chunks per channel
constexpr int CHUNK   = TSEG / TPC;    // 16 timesteps
constexpr int NCG     = Cn / CPB;      // 2 channel groups
constexpr int ROW2    = Cn / 2;        // row stride in float2 units

constexpr int NCHAIN  = Bn * NCG * LINKS;  // 1024
} // namespace

__device__ float4   g_sxn[NCHAIN * LANES]; // (sx0, sx1, sn0, sn1)
__device__ float2   g_sy [NCHAIN * LANES]; // (sy0, sy1)
__device__ unsigned g_flags[2 * NCHAIN];   // [A|B][chain]

__device__ __forceinline__ unsigned ld_acquire(const unsigned* p) {
    unsigned v;
    asm volatile("ld.acquire.gpu.global.u32 %0, [%1];" : "=r"(v) : "l"(p) : "memory");
    return v;
}
__device__ __forceinline__ void st_release(unsigned* p, unsigned v) {
    asm volatile("st.release.gpu.global.u32 [%0], %1;" :: "l"(p), "r"(v) : "memory");
}

__global__ __launch_bounds__(THREADS, 2)
void crevin_kernel(const float* __restrict__ xg,
                   const float* __restrict__ mg,
                   float* __restrict__ og)
{
    __shared__ float4 sc_xn[THREADS];   // per-(warp,lane) chunk sums
    __shared__ float2 sc_y [THREADS];
    __shared__ float4 bxn_s[LANES];     // lookback results
    __shared__ float2 by_s [LANES];

    const int tid  = threadIdx.x;
    const int c    = tid & 31;        // lane = channel pair
    const int j    = tid >> 5;        // warp = chunk index (0..15)
    const int link = blockIdx.x;      // T segment (fastest-varying bid)
    const int cg   = blockIdx.y;
    const int b    = blockIdx.z;

    // base index in float2 units
    const size_t gbase = ((size_t)b * Tn + (size_t)link * TSEG + j * CHUNK) * ROW2
                       + cg * LANES + c;
    const float2* x2 = reinterpret_cast<const float2*>(xg) + gbase;
    const float2* m2 = reinterpret_cast<const float2*>(mg) + gbase;

    // ---- phase 0: load chunk (LDG.64, 256B/warp), fused sums + mask bits ----
    float2 xr[CHUNK];
    unsigned w = 0u;                  // bits [0,16): ch0, [16,32): ch1
    float cx0 = 0.0f, cx1 = 0.0f;
#pragma unroll
    for (int i = 0; i < CHUNK; i++) {
        const float2 xv = __ldcs(x2 + i * ROW2);
        const float2 mv = __ldcs(m2 + i * ROW2);
        xr[i] = xv;
        cx0 += xv.x;
        cx1 += xv.y;
        if (mv.x == 0.0f) w |= (1u << i);           // 1 = observed
        if (mv.y == 0.0f) w |= (1u << (i + 16));
    }
    const float cn0 = (float)__popc(w & 0xFFFFu);
    const float cn1 = (float)__popc(w >> 16);

    // ---- local exclusive scan over the 16 chunks of each channel ----
    sc_xn[j * 32 + c] = make_float4(cx0, cx1, cn0, cn1);
    __syncthreads();
    float px0 = 0.0f, px1 = 0.0f, pn0 = 0.0f, pn1 = 0.0f;
    for (int k = 0; k < j; k++) {              // j warp-uniform
        const float4 v = sc_xn[k * 32 + c];
        px0 += v.x; px1 += v.y; pn0 += v.z; pn1 += v.w;
    }

    const int chain = (b * NCG + cg) * LINKS + link;
    const int cb    = chain - link;            // first link of this chain

    // ---- publish local totals for lookback A ----
    if (j == TPC - 1) {
        g_sxn[chain * LANES + c] =
            make_float4(px0 + cx0, px1 + cx1, pn0 + cn0, pn1 + cn1);
        __threadfence();
        __syncwarp();
        if (c == 0) st_release(&g_flags[chain], 1u);
    }

    // ---- lookback A: warp 0 waits for all preds, sums totals in order ----
    if (j == 0) {
        if (link > 0) {
            for (;;) {
                unsigned f = (c < link) ? ld_acquire(&g_flags[cb + c]) : 1u;
                if (__all_sync(0xffffffffu, f != 0u)) break;
            }
        }
        float bx0 = 0.0f, bx1 = 0.0f, bn0 = 0.0f, bn1 = 0.0f;
        for (int p = 0; p < link; p++) {
            const float4 v = g_sxn[(cb + p) * LANES + c];
            bx0 += v.x; bx1 += v.y; bn0 += v.z; bn1 += v.w;
        }
        bxn_s[c] = make_float4(bx0, bx1, bn0, bn1);
    }
    __syncthreads();

    // ---- phase 2: running mean, d = x - mean (in regs), chunk sums of y ----
    const float4 bq = bxn_s[c];
    float sx0 = bq.x + px0, sx1 = bq.y + px1;
    float sn0 = bq.z + pn0, sn1 = bq.w + pn1;
    float cy0 = 0.0f, cy1 = 0.0f;
#pragma unroll
    for (int i = 0; i < CHUNK; i++) {
        const float2 xv = xr[i];
        const bool ob0 = (w >> i) & 1u;
        const bool ob1 = (w >> (i + 16)) & 1u;
        sx0 += xv.x;
        sx1 += xv.y;
        if (ob0) sn0 += 1.0f;
        if (ob1) sn1 += 1.0f;
        const float m0 = __fdividef(sx0, (sn0 == 0.0f) ? 1.0f : sn0);
        const float m1 = __fdividef(sx1, (sn1 == 0.0f) ? 1.0f : sn1);
        const float d0 = xv.x - m0;
        const float d1 = xv.y - m1;
        xr[i] = make_float2(d0, d1);
        const float db0 = ob0 ? d0 : 0.0f;
        const float db1 = ob1 ? d1 : 0.0f;
        cy0 = fmaf(db0, db0, cy0);
        cy1 = fmaf(db1, db1, cy1);
    }

    sc_y[j * 32 + c] = make_float2(cy0, cy1);
    __syncthreads();
    float py0 = 0.0f, py1 = 0.0f;
    for (int k = 0; k < j; k++) {
        const float2 v = sc_y[k * 32 + c];
        py0 += v.x; py1 += v.y;
    }

    // ---- publish local y totals; lookback B ----
    if (j == TPC - 1) {
        g_sy[chain * LANES + c] = make_float2(py0 + cy0, py1 + cy1);
        __threadfence();
        __syncwarp();
        if (c == 0) st_release(&g_flags[NCHAIN + chain], 1u);
    }
    if (j == 0) {
        if (link > 0) {
            for (;;) {
                unsigned f = (c < link) ? ld_acquire(&g_flags[NCHAIN + cb + c]) : 1u;
                if (__all_sync(0xffffffffu, f != 0u)) break;
            }
        }
        float by0 = 0.0f, by1 = 0.0f;
        for (int p = 0; p < link; p++) {
            const float2 v = g_sy[(cb + p) * LANES + c];
            by0 += v.x; by1 += v.y;
        }
        by_s[c] = make_float2(by0, by1);
    }
    __syncthreads();

    // ---- phase 3: running variance, normalize + clamp, coalesced store ----
    const float2 bu = by_s[c];
    float sy0 = bu.x + py0, sy1 = bu.y + py1;
    float t0  = bq.z + pn0, t1  = bq.w + pn1;   // running n again
    float2* o2 = reinterpret_cast<float2*>(og) + gbase;
#pragma unroll
    for (int i = 0; i < CHUNK; i++) {
        const float2 dv = xr[i];
        const bool ob0 = (w >> i) & 1u;
        const bool ob1 = (w >> (i + 16)) & 1u;
        if (ob0) t0 += 1.0f;
        if (ob1) t1 += 1.0f;
        const float db0 = ob0 ? dv.x : 0.0f;
        const float db1 = ob1 ? dv.y : 0.0f;
        sy0 = fmaf(db0, db0, sy0);
        sy1 = fmaf(db1, db1, sy1);
        const float v0 = __fdividef(sy0, (t0 == 0.0f) ? 1.0f : t0);
        const float v1 = __fdividef(sy1, (t1 == 0.0f) ? 1.0f : t1);
        // std > 1e-5  <=>  var > 1e-10 ; else std := 1
        const float is0 = (v0 > 1e-10f) ? rsqrtf(v0) : 1.0f;
        const float is1 = (v1 > 1e-10f) ? rsqrtf(v1) : 1.0f;
        float r0 = dv.x * is0;
        float r1 = dv.y * is1;
        r0 = fminf(100.0f, fmaxf(-100.0f, r0));
        r1 = fminf(100.0f, fmaxf(-100.0f, r1));
        __stcs(o2 + i * ROW2, make_float2(r0, r1));
    }
}

extern "C" void kernel_launch(void* const* d_in, const int* in_sizes, int n_in,
                              void* d_out, int out_size) {
    const float* x = (const float*)d_in[0];
    const float* m = (const float*)d_in[1];
    float*       o = (float*)d_out;

    static void* fptr = nullptr;
    if (!fptr) cudaGetSymbolAddress(&fptr, g_flags);
    cudaMemsetAsync(fptr, 0, sizeof(unsigned) * 2 * NCHAIN, 0);

    dim3 grid(LINKS, NCG, Bn);   // link fastest -> chain members co-resident,
                                 // preds always at lower bid (deadlock-free)
    crevin_kernel<<<grid, THREADS>>>(x, m, o);
}